// round 5
// baseline (speedup 1.0000x reference)
#include <cuda_runtime.h>
#include <cstdint>

#define NBKT 4096
#define BKT_SHIFT 4          // bucket = src >> 4 : 16 rows = 8KB per bucket
#define MAX_E 655360

// Scratch (no allocations allowed)
__device__ int  g_cnt[NBKT];
__device__ int  g_cur[NBKT];
__device__ int4 g_pack[MAX_E];   // {eid, src, dst, pad} in src-bucket-sorted order

__global__ void zero_kernel() {
    int i = blockIdx.x * blockDim.x + threadIdx.x;
    if (i < NBKT) g_cnt[i] = 0;
}

__global__ void hist_kernel(const int* __restrict__ src, int E) {
    int e = blockIdx.x * blockDim.x + threadIdx.x;
    if (e < E) atomicAdd(&g_cnt[src[e] >> BKT_SHIFT], 1);
}

// Exclusive scan of 4096 bins: 1024 threads, 4 bins each.
__global__ void scan_kernel() {
    __shared__ int part[1024];
    int t = threadIdx.x;
    int c0 = g_cnt[t*4], c1 = g_cnt[t*4+1], c2 = g_cnt[t*4+2], c3 = g_cnt[t*4+3];
    int s = c0 + c1 + c2 + c3;
    part[t] = s;
    __syncthreads();
    for (int off = 1; off < 1024; off <<= 1) {
        int v = (t >= off) ? part[t - off] : 0;
        __syncthreads();
        part[t] += v;
        __syncthreads();
    }
    int excl = part[t] - s;
    g_cur[t*4]   = excl;
    g_cur[t*4+1] = excl + c0;
    g_cur[t*4+2] = excl + c0 + c1;
    g_cur[t*4+3] = excl + c0 + c1 + c2;
}

__global__ void scatter_kernel(const int* __restrict__ src,
                               const int* __restrict__ dst, int E) {
    int e = blockIdx.x * blockDim.x + threadIdx.x;
    if (e < E) {
        int s = src[e], d = dst[e];
        int p = atomicAdd(&g_cur[s >> BKT_SHIFT], 1);
        g_pack[p] = make_int4(e, s, d, 0);
    }
}

// Main: 4 edges per warp (8 lanes each), each block owns 256 contiguous
// sorted positions (8 warps x 32-position strips, 8 iterations of 4).
// Sorted order => same src rows recur within a block => L1 hits.
__global__ __launch_bounds__(256) void udotv_main(
    const float4* __restrict__ h,   // [N,32] float4 view of [N,128] f32
    float* __restrict__ out, int E)
{
    int w     = threadIdx.x >> 5;
    int lane  = threadIdx.x & 31;
    int group = lane >> 3;
    int gl    = lane & 7;
    int base  = blockIdx.x * 256 + w * 32;

    #pragma unroll
    for (int it = 0; it < 8; it++) {
        int p = base + it * 4 + group;
        bool valid = (p < E);
        int pc = valid ? p : (E - 1);

        int4 pk = __ldg(&g_pack[pc]);   // broadcast within group

        const float4* pa = h + (long long)pk.y * 32 + gl;
        const float4* pb = h + (long long)pk.z * 32 + gl;

        float4 a0 = __ldg(pa);      float4 a1 = __ldg(pa + 8);
        float4 a2 = __ldg(pa + 16); float4 a3 = __ldg(pa + 24);
        float4 b0 = __ldg(pb);      float4 b1 = __ldg(pb + 8);
        float4 b2 = __ldg(pb + 16); float4 b3 = __ldg(pb + 24);

        float s0 = fmaf(a0.x, b0.x, fmaf(a0.y, b0.y, fmaf(a0.z, b0.z, a0.w * b0.w)));
        float s1 = fmaf(a1.x, b1.x, fmaf(a1.y, b1.y, fmaf(a1.z, b1.z, a1.w * b1.w)));
        float s2 = fmaf(a2.x, b2.x, fmaf(a2.y, b2.y, fmaf(a2.z, b2.z, a2.w * b2.w)));
        float s3 = fmaf(a3.x, b3.x, fmaf(a3.y, b3.y, fmaf(a3.z, b3.z, a3.w * b3.w)));
        float sum = (s0 + s1) + (s2 + s3);

        sum += __shfl_xor_sync(0xffffffffu, sum, 1);
        sum += __shfl_xor_sync(0xffffffffu, sum, 2);
        sum += __shfl_xor_sync(0xffffffffu, sum, 4);

        if (gl == 0 && valid) out[pk.x] = sum;
    }
}

extern "C" void kernel_launch(void* const* d_in, const int* in_sizes, int n_in,
                              void* d_out, int out_size)
{
    const float4* h  = (const float4*)d_in[0];
    const int* src   = (const int*)d_in[1];
    const int* dst   = (const int*)d_in[2];
    float* out       = (float*)d_out;

    int E = in_sizes[1];   // 640000

    zero_kernel<<<(NBKT + 255) / 256, 256>>>();
    hist_kernel<<<(E + 255) / 256, 256>>>(src, E);
    scan_kernel<<<1, 1024>>>();
    scatter_kernel<<<(E + 255) / 256, 256>>>(src, dst, E);
    udotv_main<<<(E + 255) / 256, 256>>>(h, out, E);
}

// round 6
// speedup vs baseline: 2.1107x; 2.1107x over previous
#include <cuda_runtime.h>
#include <cstdint>

// 8 edges per warp: 4 groups of 8 lanes, each group handles edges e and e+4.
// All 16 row loads (LDG.128) issued before any FMA -> MLP=16 per lane.
// 3-step butterfly per edge; group leaders write 8 consecutive floats/warp.
__global__ __launch_bounds__(256) void udotv_kernel(
    const float4* __restrict__ h,   // [N, 32] float4 view of [N,128] f32
    const int* __restrict__ src,    // [E] int32
    const int* __restrict__ dst,    // [E] int32
    float* __restrict__ out,        // [E]
    int n_edges)
{
    int warp_id = (blockIdx.x * blockDim.x + threadIdx.x) >> 5;
    int lane  = threadIdx.x & 31;
    int group = lane >> 3;          // 0..3
    int gl    = lane & 7;           // lane within group

    long long e0 = (long long)warp_id * 8 + group;  // first edge of this group
    long long e1 = e0 + 4;                          // second edge
    bool v0 = (e0 < n_edges);
    bool v1 = (e1 < n_edges);
    long long e0c = v0 ? e0 : (n_edges - 1);
    long long e1c = v1 ? e1 : (n_edges - 1);

    int s0 = __ldg(&src[e0c]);
    int d0 = __ldg(&dst[e0c]);
    int s1 = __ldg(&src[e1c]);
    int d1 = __ldg(&dst[e1c]);

    const float4* pa = h + (long long)s0 * 32 + gl;
    const float4* pb = h + (long long)d0 * 32 + gl;
    const float4* pc = h + (long long)s1 * 32 + gl;
    const float4* pd = h + (long long)d1 * 32 + gl;

    // 16 independent 16B loads, front-batched
    float4 a0 = __ldg(pa);      float4 a1 = __ldg(pa + 8);
    float4 a2 = __ldg(pa + 16); float4 a3 = __ldg(pa + 24);
    float4 b0 = __ldg(pb);      float4 b1 = __ldg(pb + 8);
    float4 b2 = __ldg(pb + 16); float4 b3 = __ldg(pb + 24);
    float4 c0 = __ldg(pc);      float4 c1 = __ldg(pc + 8);
    float4 c2 = __ldg(pc + 16); float4 c3 = __ldg(pc + 24);
    float4 d0v = __ldg(pd);     float4 d1v = __ldg(pd + 8);
    float4 d2v = __ldg(pd + 16);float4 d3v = __ldg(pd + 24);

    // Edge 0 dot
    float x0 = fmaf(a0.x, b0.x, fmaf(a0.y, b0.y, fmaf(a0.z, b0.z, a0.w * b0.w)));
    float x1 = fmaf(a1.x, b1.x, fmaf(a1.y, b1.y, fmaf(a1.z, b1.z, a1.w * b1.w)));
    float x2 = fmaf(a2.x, b2.x, fmaf(a2.y, b2.y, fmaf(a2.z, b2.z, a2.w * b2.w)));
    float x3 = fmaf(a3.x, b3.x, fmaf(a3.y, b3.y, fmaf(a3.z, b3.z, a3.w * b3.w)));
    float sum0 = (x0 + x1) + (x2 + x3);

    // Edge 1 dot
    float y0 = fmaf(c0.x, d0v.x, fmaf(c0.y, d0v.y, fmaf(c0.z, d0v.z, c0.w * d0v.w)));
    float y1 = fmaf(c1.x, d1v.x, fmaf(c1.y, d1v.y, fmaf(c1.z, d1v.z, c1.w * d1v.w)));
    float y2 = fmaf(c2.x, d2v.x, fmaf(c2.y, d2v.y, fmaf(c2.z, d2v.z, c2.w * d2v.w)));
    float y3 = fmaf(c3.x, d3v.x, fmaf(c3.y, d3v.y, fmaf(c3.z, d3v.z, c3.w * d3v.w)));
    float sum1 = (y0 + y1) + (y2 + y3);

    // Butterfly reductions within each 8-lane group (interleaved, independent)
    sum0 += __shfl_xor_sync(0xffffffffu, sum0, 1);
    sum1 += __shfl_xor_sync(0xffffffffu, sum1, 1);
    sum0 += __shfl_xor_sync(0xffffffffu, sum0, 2);
    sum1 += __shfl_xor_sync(0xffffffffu, sum1, 2);
    sum0 += __shfl_xor_sync(0xffffffffu, sum0, 4);
    sum1 += __shfl_xor_sync(0xffffffffu, sum1, 4);

    if (gl == 0) {
        if (v0) out[e0] = sum0;
        if (v1) out[e1] = sum1;
    }
}

extern "C" void kernel_launch(void* const* d_in, const int* in_sizes, int n_in,
                              void* d_out, int out_size)
{
    const float4* h = (const float4*)d_in[0];
    const int* src  = (const int*)d_in[1];
    const int* dst  = (const int*)d_in[2];
    float* out      = (float*)d_out;

    int n_edges = in_sizes[1];          // E = 640000
    int edges_per_block = 8 * 8;        // 8 warps x 8 edges
    int blocks = (n_edges + edges_per_block - 1) / edges_per_block;
    udotv_kernel<<<blocks, 256>>>(h, src, dst, out, n_edges);
}